// round 16
// baseline (speedup 1.0000x reference)
#include <cuda_runtime.h>
#include <math.h>

#define NN 100000
#define NE 3200000
#define INF_ 128
#define F1 32
#define F2 16

typedef unsigned long long ull;

// ---------------- scratch (static device globals; zero-init at module load) ----------------
__device__ ull   g_deg64[NN];         // packed: (count << 40) | round(ew * 2^30) sum
__device__ float g_dinv[NN];          // rsqrt(wsum + 1), written by scanA
__device__ int   g_cnt[NN];           // decoded counts, written by scanA
__device__ int   g_row[NN];           // CSR row start (arrival-order block offsets)
__device__ int   g_cur[NN];           // scatter cursors
__device__ int2  g_cedge[NE];         // (src, norm-as-int-bits) per CSR slot
__device__ float g_h1[NN * F1];       // x @ W1
__device__ float g_h2[NN * F2];       // hrelu @ W2 (pre-bias)
__device__ float g_q[NN];             // dot(hrelu, fc2_w[0:32]) per node
__device__ int   g_total;             // running block-offset counter (reset in tail)

#define NB 391                        // node blocks of 256 (also gemm1 tile blocks)
#define E4_BLOCKS 3125                // edge blocks (256 thr, 4 edges/thr)

// ---------------- f32x2 packed-FMA helpers (sm_103a FFMA2) ----------------
__device__ __forceinline__ ull pack2(float a, float b) {
    ull r; asm("mov.b64 %0, {%1, %2};" : "=l"(r) : "f"(a), "f"(b)); return r;
}
__device__ __forceinline__ ull fma2(ull a, ull b, ull c) {
    ull d; asm("fma.rn.f32x2 %0, %1, %2, %3;" : "=l"(d) : "l"(a), "l"(b), "l"(c)); return d;
}
__device__ __forceinline__ float2 unpack2(ull v) {
    float x, y; asm("mov.b64 {%0, %1}, %2;" : "=f"(x), "=f"(y) : "l"(v));
    return make_float2(x, y);
}

// ---------------- fat kernel: tiled gemm1 (bid < NB) + packed 64-bit count ----------------
__global__ void __launch_bounds__(256) k_gemm1_count(
        const float* __restrict__ x, const float* __restrict__ W1,
        const int* __restrict__ ei, const float* __restrict__ ew) {
    __shared__ __align__(16) float sW[INF_ * F1];   // [k][f]
    __shared__ __align__(16) float sX[32 * 256];    // [k_local][node_local]
    int bid = blockIdx.x;
    int tid = threadIdx.x;
    if (bid < NB) {
        for (int i = tid; i < INF_ * F1; i += 256) sW[i] = W1[i];
        int nbase = bid * 256;
        int ng = tid >> 2;          // node group 0..63 (4 nodes each)
        int fg = tid & 3;           // feature group 0..3 (8 feats each)
        int f0 = fg * 8;
        ull acc[4][4];
#pragma unroll
        for (int c = 0; c < 4; c++)
#pragma unroll
            for (int p = 0; p < 4; p++) acc[c][p] = 0ull;

        for (int kt = 0; kt < 4; kt++) {
            __syncthreads();
#pragma unroll
            for (int j = 0; j < 8; j++) {
                int flat = tid * 8 + j;     // 0..2047
                int nl = flat >> 3;         // node local 0..255
                int k4 = flat & 7;          // float4 index 0..7
                int n = nbase + nl;
                float4 v = make_float4(0.f, 0.f, 0.f, 0.f);
                if (n < NN)
                    v = *(const float4*)(x + (size_t)n * INF_ + kt * 32 + k4 * 4);
                sX[(k4 * 4 + 0) * 256 + nl] = v.x;
                sX[(k4 * 4 + 1) * 256 + nl] = v.y;
                sX[(k4 * 4 + 2) * 256 + nl] = v.z;
                sX[(k4 * 4 + 3) * 256 + nl] = v.w;
            }
            __syncthreads();
#pragma unroll
            for (int k = 0; k < 32; k++) {
                float4 xv = *(const float4*)&sX[k * 256 + ng * 4];
                const float4* wr = (const float4*)&sW[(kt * 32 + k) * F1 + f0];
                float4 w0 = wr[0], w1 = wr[1];
                ull wp0 = pack2(w0.x, w0.y), wp1 = pack2(w0.z, w0.w);
                ull wp2 = pack2(w1.x, w1.y), wp3 = pack2(w1.z, w1.w);
                float xs[4] = {xv.x, xv.y, xv.z, xv.w};
#pragma unroll
                for (int c = 0; c < 4; c++) {
                    ull xp = pack2(xs[c], xs[c]);
                    acc[c][0] = fma2(xp, wp0, acc[c][0]);
                    acc[c][1] = fma2(xp, wp1, acc[c][1]);
                    acc[c][2] = fma2(xp, wp2, acc[c][2]);
                    acc[c][3] = fma2(xp, wp3, acc[c][3]);
                }
            }
        }
#pragma unroll
        for (int c = 0; c < 4; c++) {
            int n = nbase + ng * 4 + c;
            if (n < NN) {
                float2 v0 = unpack2(acc[c][0]), v1 = unpack2(acc[c][1]);
                float2 v2 = unpack2(acc[c][2]), v3 = unpack2(acc[c][3]);
                float4* o = (float4*)(g_h1 + (size_t)n * F1 + f0);
                o[0] = make_float4(v0.x, v0.y, v1.x, v1.y);
                o[1] = make_float4(v2.x, v2.y, v3.x, v3.y);
            }
        }
    } else {
        // ---- 4 edges per thread: ONE packed 64-bit REDG per edge ----
        int e = ((bid - NB) * 256 + tid) * 4;
        if (e >= NE) return;
        int4   d4 = *(const int4*)  (ei + NE + e);
        float4 w4 = *(const float4*)(ew + e);
        const float SC = 1073741824.0f;   // 2^30
        atomicAdd(&g_deg64[d4.x], (1ull << 40) + (ull)__float2uint_rn(w4.x * SC));
        atomicAdd(&g_deg64[d4.y], (1ull << 40) + (ull)__float2uint_rn(w4.y * SC));
        atomicAdd(&g_deg64[d4.z], (1ull << 40) + (ull)__float2uint_rn(w4.z * SC));
        atomicAdd(&g_deg64[d4.w], (1ull << 40) + (ull)__float2uint_rn(w4.w * SC));
    }
}

// ---- one-kernel scan: decode packed deg, block scan, arrival-order offsets ----
__global__ void k_scanA() {
    __shared__ int sh[256];
    __shared__ int s_off;
    int t = threadIdx.x;
    int i = blockIdx.x * 256 + t;
    int cnt = 0;
    float wsum = 0.f;
    if (i < NN) {
        ull v = g_deg64[i];
        cnt = (int)(v >> 40);
        wsum = (float)(v & ((1ull << 40) - 1)) * (1.0f / 1073741824.0f);
    }
    sh[t] = cnt;
    __syncthreads();
    for (int off = 1; off < 256; off <<= 1) {
        int u = (t >= off) ? sh[t - off] : 0;
        __syncthreads();
        sh[t] += u;
        __syncthreads();
    }
    if (t == 255) s_off = atomicAdd(&g_total, sh[255]);
    __syncthreads();
    if (i < NN) {
        int ex = s_off + sh[t] - cnt;
        g_row[i] = ex;
        g_cur[i] = ex;
        g_cnt[i] = cnt;
        g_dinv[i] = rsqrtf(wsum + 1.0f);
    }
}

// 4 edges per thread: cursor-atomic scatter into CSR
__global__ void k_scatter(const int* __restrict__ ei, const float* __restrict__ ew) {
    int e = (blockIdx.x * blockDim.x + threadIdx.x) * 4;
    if (e >= NE) return;
    int4   s4 = *(const int4*)  (ei + e);
    int4   d4 = *(const int4*)  (ei + NE + e);
    float4 w4 = *(const float4*)(ew + e);
    float n0 = g_dinv[s4.x] * w4.x * g_dinv[d4.x];
    float n1 = g_dinv[s4.y] * w4.y * g_dinv[d4.y];
    float n2 = g_dinv[s4.z] * w4.z * g_dinv[d4.z];
    float n3 = g_dinv[s4.w] * w4.w * g_dinv[d4.w];
    int p0 = atomicAdd(&g_cur[d4.x], 1);
    int p1 = atomicAdd(&g_cur[d4.y], 1);
    int p2 = atomicAdd(&g_cur[d4.z], 1);
    int p3 = atomicAdd(&g_cur[d4.w], 1);
    g_cedge[p0] = make_int2(s4.x, __float_as_int(n0));
    g_cedge[p1] = make_int2(s4.y, __float_as_int(n1));
    g_cedge[p2] = make_int2(s4.z, __float_as_int(n2));
    g_cedge[p3] = make_int2(s4.w, __float_as_int(n3));
}

// FUSED layer1 agg + relu + gemm2 + fc-head dot: warp-per-node.
// Edge loop: HALF-warp per edge, float2 per lane. Full windows unclamped
// (no predication), then exactly one clamped remainder window.
__global__ void __launch_bounds__(256) k_agg1_fused(
        const float* __restrict__ b1, const float* __restrict__ W2,
        const float* __restrict__ fc2_w) {
    const unsigned FULL = 0xffffffffu;
    __shared__ float sW2[F1 * F2];    // 2 KB [k][f]
    __shared__ float sH[8][F1];       // per-warp hrelu slab
    int tid = threadIdx.x;
    for (int i = tid; i < F1 * F2; i += 256) sW2[i] = W2[i];
    __syncthreads();
    int lane = tid & 31;
    int wid = tid >> 5;
    int n = blockIdx.x * 8 + wid;
    if (n >= NN) return;
    int f2 = lane & 15;      // features 2f2, 2f2+1
    int half = lane >> 4;    // edge interleave x2
    int beg = g_row[n];
    int cnt = g_cnt[n];
    int nfull = cnt >> 4;    // full 16-edge windows
    int rem = cnt & 15;
    float ax0 = 0.f, ay0 = 0.f, ax1 = 0.f, ay1 = 0.f;
    int base = beg + half;
    for (int it = 0; it < nfull; it++, base += 16) {
        int2 e0 = g_cedge[base];
        int2 e1 = g_cedge[base + 2];
        int2 e2 = g_cedge[base + 4];
        int2 e3 = g_cedge[base + 6];
        int2 e4 = g_cedge[base + 8];
        int2 e5 = g_cedge[base + 10];
        int2 e6 = g_cedge[base + 12];
        int2 e7 = g_cedge[base + 14];
        float2 h0 = *(const float2*)(g_h1 + (unsigned)e0.x * F1 + 2 * f2);
        float2 h1 = *(const float2*)(g_h1 + (unsigned)e1.x * F1 + 2 * f2);
        float2 h2 = *(const float2*)(g_h1 + (unsigned)e2.x * F1 + 2 * f2);
        float2 h3 = *(const float2*)(g_h1 + (unsigned)e3.x * F1 + 2 * f2);
        float2 h4 = *(const float2*)(g_h1 + (unsigned)e4.x * F1 + 2 * f2);
        float2 h5 = *(const float2*)(g_h1 + (unsigned)e5.x * F1 + 2 * f2);
        float2 h6 = *(const float2*)(g_h1 + (unsigned)e6.x * F1 + 2 * f2);
        float2 h7 = *(const float2*)(g_h1 + (unsigned)e7.x * F1 + 2 * f2);
        float w0 = __int_as_float(e0.y), w1 = __int_as_float(e1.y);
        float w2 = __int_as_float(e2.y), w3 = __int_as_float(e3.y);
        float w4 = __int_as_float(e4.y), w5 = __int_as_float(e5.y);
        float w6 = __int_as_float(e6.y), w7 = __int_as_float(e7.y);
        ax0 += w0 * h0.x; ay0 += w0 * h0.y;
        ax1 += w1 * h1.x; ay1 += w1 * h1.y;
        ax0 += w2 * h2.x; ay0 += w2 * h2.y;
        ax1 += w3 * h3.x; ay1 += w3 * h3.y;
        ax0 += w4 * h4.x; ay0 += w4 * h4.y;
        ax1 += w5 * h5.x; ay1 += w5 * h5.y;
        ax0 += w6 * h6.x; ay0 += w6 * h6.y;
        ax1 += w7 * h7.x; ay1 += w7 * h7.y;
    }
    if (rem) {
        int end = beg + cnt;
        int i0 = base,      i1 = base + 2,  i2 = base + 4,  i3 = base + 6;
        int i4 = base + 8,  i5 = base + 10, i6 = base + 12, i7 = base + 14;
        bool v0 = i0 < end, v1 = i1 < end, v2 = i2 < end, v3 = i3 < end;
        bool v4 = i4 < end, v5 = i5 < end, v6 = i6 < end, v7 = i7 < end;
        int2 e0 = g_cedge[v0 ? i0 : 0];
        int2 e1 = g_cedge[v1 ? i1 : 0];
        int2 e2 = g_cedge[v2 ? i2 : 0];
        int2 e3 = g_cedge[v3 ? i3 : 0];
        int2 e4 = g_cedge[v4 ? i4 : 0];
        int2 e5 = g_cedge[v5 ? i5 : 0];
        int2 e6 = g_cedge[v6 ? i6 : 0];
        int2 e7 = g_cedge[v7 ? i7 : 0];
        float2 h0 = *(const float2*)(g_h1 + (unsigned)e0.x * F1 + 2 * f2);
        float2 h1 = *(const float2*)(g_h1 + (unsigned)e1.x * F1 + 2 * f2);
        float2 h2 = *(const float2*)(g_h1 + (unsigned)e2.x * F1 + 2 * f2);
        float2 h3 = *(const float2*)(g_h1 + (unsigned)e3.x * F1 + 2 * f2);
        float2 h4 = *(const float2*)(g_h1 + (unsigned)e4.x * F1 + 2 * f2);
        float2 h5 = *(const float2*)(g_h1 + (unsigned)e5.x * F1 + 2 * f2);
        float2 h6 = *(const float2*)(g_h1 + (unsigned)e6.x * F1 + 2 * f2);
        float2 h7 = *(const float2*)(g_h1 + (unsigned)e7.x * F1 + 2 * f2);
        float w0 = v0 ? __int_as_float(e0.y) : 0.f;
        float w1 = v1 ? __int_as_float(e1.y) : 0.f;
        float w2 = v2 ? __int_as_float(e2.y) : 0.f;
        float w3 = v3 ? __int_as_float(e3.y) : 0.f;
        float w4 = v4 ? __int_as_float(e4.y) : 0.f;
        float w5 = v5 ? __int_as_float(e5.y) : 0.f;
        float w6 = v6 ? __int_as_float(e6.y) : 0.f;
        float w7 = v7 ? __int_as_float(e7.y) : 0.f;
        ax0 += w0 * h0.x; ay0 += w0 * h0.y;
        ax1 += w1 * h1.x; ay1 += w1 * h1.y;
        ax0 += w2 * h2.x; ay0 += w2 * h2.y;
        ax1 += w3 * h3.x; ay1 += w3 * h3.y;
        ax0 += w4 * h4.x; ay0 += w4 * h4.y;
        ax1 += w5 * h5.x; ay1 += w5 * h5.y;
        ax0 += w6 * h6.x; ay0 += w6 * h6.y;
        ax1 += w7 * h7.x; ay1 += w7 * h7.y;
    }
    float ax = ax0 + ax1, ay = ay0 + ay1;
    ax += __shfl_down_sync(FULL, ax, 16);
    ay += __shfl_down_sync(FULL, ay, 16);
    float di = g_dinv[n];
    float d2 = di * di;
    float2 hs = *(const float2*)(g_h1 + (unsigned)n * F1 + 2 * f2);
    // hrelu features 2f2, 2f2+1 — valid on lanes 0..15
    float hx = fmaxf(ax + d2 * hs.x + b1[2 * f2], 0.f);
    float hy = fmaxf(ay + d2 * hs.y + b1[2 * f2 + 1], 0.f);
    if (lane < 16) {
        sH[wid][2 * f2] = hx;
        sH[wid][2 * f2 + 1] = hy;
    }
    __syncwarp();
    // q = dot(hrelu, fc2_w[0:32]) : reduce within 16-lane group
    float p = (lane < 16) ? hx * fc2_w[2 * f2] + hy * fc2_w[2 * f2 + 1] : 0.f;
    p += __shfl_xor_sync(FULL, p, 8);
    p += __shfl_xor_sync(FULL, p, 4);
    p += __shfl_xor_sync(FULL, p, 2);
    p += __shfl_xor_sync(FULL, p, 1);
    if (lane == 0) g_q[n] = p;
    // h2[f] = sum_k hrelu[k]*W2[k][f] : f = lane&15, k-range split by half, fold
    const float* s = sH[wid];
    int f = lane & 15;
    int k0 = half * 16;
    float acc = 0.f, accB = 0.f;
#pragma unroll
    for (int k = 0; k < 16; k += 2) {
        acc  += s[k0 + k]     * sW2[(k0 + k) * F2 + f];
        accB += s[k0 + k + 1] * sW2[(k0 + k + 1) * F2 + f];
    }
    acc += accB;
    acc += __shfl_down_sync(FULL, acc, 16);
    if (lane < 16) g_h2[(unsigned)n * F2 + f] = acc;
}

// layer2 aggregation + FC head + tail zeroing; warp-per-node.
// Edge loop: 4 lanes per edge, float4 per lane. Full 32-edge windows unclamped,
// one clamped remainder window.
__global__ void k_agg2_final(const float* __restrict__ b2,
                             const float* __restrict__ fc1_w, const float* __restrict__ fc1_b,
                             const float* __restrict__ fc2_w, const float* __restrict__ fc2_b,
                             float* __restrict__ out) {
    const unsigned FULL = 0xffffffffu;
    int lane = threadIdx.x & 31;
    int n = blockIdx.x * (blockDim.x >> 5) + (threadIdx.x >> 5);
    if (n >= NN) return;
    int oc = lane >> 2;      // octant 0..7 (edge interleave)
    int f4 = lane & 3;       // features 4*f4 .. 4*f4+3 (of 16)
    int beg = g_row[n];
    int cnt = g_cnt[n];
    int nfull = cnt >> 5;
    int rem = cnt & 31;
    float4 a0 = make_float4(0.f, 0.f, 0.f, 0.f);
    float4 a1 = make_float4(0.f, 0.f, 0.f, 0.f);
    int base = beg + oc;
    for (int it = 0; it < nfull; it++, base += 32) {
        int2 e0 = g_cedge[base];
        int2 e1 = g_cedge[base + 8];
        int2 e2 = g_cedge[base + 16];
        int2 e3 = g_cedge[base + 24];
        float4 h0 = *(const float4*)(g_h2 + (unsigned)e0.x * F2 + 4 * f4);
        float4 h1 = *(const float4*)(g_h2 + (unsigned)e1.x * F2 + 4 * f4);
        float4 h2 = *(const float4*)(g_h2 + (unsigned)e2.x * F2 + 4 * f4);
        float4 h3 = *(const float4*)(g_h2 + (unsigned)e3.x * F2 + 4 * f4);
        float w0 = __int_as_float(e0.y), w1 = __int_as_float(e1.y);
        float w2 = __int_as_float(e2.y), w3 = __int_as_float(e3.y);
        a0.x += w0 * h0.x; a0.y += w0 * h0.y; a0.z += w0 * h0.z; a0.w += w0 * h0.w;
        a1.x += w1 * h1.x; a1.y += w1 * h1.y; a1.z += w1 * h1.z; a1.w += w1 * h1.w;
        a0.x += w2 * h2.x; a0.y += w2 * h2.y; a0.z += w2 * h2.z; a0.w += w2 * h2.w;
        a1.x += w3 * h3.x; a1.y += w3 * h3.y; a1.z += w3 * h3.z; a1.w += w3 * h3.w;
    }
    if (rem) {
        int end = beg + cnt;
        int i0 = base, i1 = base + 8, i2 = base + 16, i3 = base + 24;
        bool v0 = i0 < end, v1 = i1 < end, v2 = i2 < end, v3 = i3 < end;
        int2 e0 = g_cedge[v0 ? i0 : 0];
        int2 e1 = g_cedge[v1 ? i1 : 0];
        int2 e2 = g_cedge[v2 ? i2 : 0];
        int2 e3 = g_cedge[v3 ? i3 : 0];
        float w0 = v0 ? __int_as_float(e0.y) : 0.f;
        float w1 = v1 ? __int_as_float(e1.y) : 0.f;
        float w2 = v2 ? __int_as_float(e2.y) : 0.f;
        float w3 = v3 ? __int_as_float(e3.y) : 0.f;
        float4 h0 = *(const float4*)(g_h2 + (unsigned)e0.x * F2 + 4 * f4);
        float4 h1 = *(const float4*)(g_h2 + (unsigned)e1.x * F2 + 4 * f4);
        float4 h2 = *(const float4*)(g_h2 + (unsigned)e2.x * F2 + 4 * f4);
        float4 h3 = *(const float4*)(g_h2 + (unsigned)e3.x * F2 + 4 * f4);
        a0.x += w0 * h0.x; a0.y += w0 * h0.y; a0.z += w0 * h0.z; a0.w += w0 * h0.w;
        a1.x += w1 * h1.x; a1.y += w1 * h1.y; a1.z += w1 * h1.z; a1.w += w1 * h1.w;
        a0.x += w2 * h2.x; a0.y += w2 * h2.y; a0.z += w2 * h2.z; a0.w += w2 * h2.w;
        a1.x += w3 * h3.x; a1.y += w3 * h3.y; a1.z += w3 * h3.z; a1.w += w3 * h3.w;
    }
    float4 a = make_float4(a0.x + a1.x, a0.y + a1.y, a0.z + a1.z, a0.w + a1.w);
    a.x += __shfl_down_sync(FULL, a.x, 16);
    a.y += __shfl_down_sync(FULL, a.y, 16);
    a.z += __shfl_down_sync(FULL, a.z, 16);
    a.w += __shfl_down_sync(FULL, a.w, 16);
    a.x += __shfl_down_sync(FULL, a.x, 8);
    a.y += __shfl_down_sync(FULL, a.y, 8);
    a.z += __shfl_down_sync(FULL, a.z, 8);
    a.w += __shfl_down_sync(FULL, a.w, 8);
    a.x += __shfl_down_sync(FULL, a.x, 4);
    a.y += __shfl_down_sync(FULL, a.y, 4);
    a.z += __shfl_down_sync(FULL, a.z, 4);
    a.w += __shfl_down_sync(FULL, a.w, 4);    // lanes 0..3 hold full feature sums
    float di = g_dinv[n];
    float d2 = di * di;
    float4 hs = *(const float4*)(g_h2 + (unsigned)n * F2 + 4 * f4);
    float x0 = a.x + d2 * hs.x + b2[4 * f4 + 0];
    float x1v = a.y + d2 * hs.y + b2[4 * f4 + 1];
    float x2v = a.z + d2 * hs.z + b2[4 * f4 + 2];
    float x3 = a.w + d2 * hs.w + b2[4 * f4 + 3];
    // x1f = dot(x2[0:16], fc1_w): per-lane partial over 4 feats, reduce 4-lane group
    float p = x0 * fc1_w[4 * f4] + x1v * fc1_w[4 * f4 + 1]
            + x2v * fc1_w[4 * f4 + 2] + x3 * fc1_w[4 * f4 + 3];
    p += __shfl_xor_sync(FULL, p, 2);
    p += __shfl_xor_sync(FULL, p, 1);         // lanes 0..3 correct
    float x1f = p + fc1_b[0];
    if (lane == 0) {
        float c = 1.0f / (1.0f + expf(-x1f));
        float r = g_q[n] + c * fc2_w[32] + fc2_b[0];
        out[n] = r;
        out[NN + n] = x1f;
    }
    // tail zeroing for the NEXT replay (values already consumed above)
    if (lane == 4) g_deg64[n] = 0ull;
    if (n == 0 && lane == 12) g_total = 0;
}

// ---------------- launch ----------------
extern "C" void kernel_launch(void* const* d_in, const int* in_sizes, int n_in,
                              void* d_out, int out_size) {
    const float* x     = (const float*)d_in[0];
    const int*   ei    = (const int*)  d_in[1];
    const float* ew    = (const float*)d_in[2];
    const float* W1    = (const float*)d_in[3];
    const float* b1    = (const float*)d_in[4];
    const float* W2    = (const float*)d_in[5];
    const float* b2    = (const float*)d_in[6];
    const float* fc1w  = (const float*)d_in[7];
    const float* fc1b  = (const float*)d_in[8];
    const float* fc2w  = (const float*)d_in[9];
    const float* fc2b  = (const float*)d_in[10];
    float* out = (float*)d_out;

    const int TB = 256;
    const int gW = (NN * 32 + TB - 1) / TB;   // warp-per-node: 8 nodes/block
    (void)in_sizes; (void)n_in; (void)out_size;

    k_gemm1_count<<<NB + E4_BLOCKS, TB>>>(x, W1, ei, ew);          // 1
    k_scanA<<<NB, 256>>>();                                        // 2
    k_scatter<<<E4_BLOCKS, TB>>>(ei, ew);                          // 3
    k_agg1_fused<<<gW, TB>>>(b1, W2, fc2w);                        // 4 -> profiled slot
    k_agg2_final<<<gW, TB>>>(b2, fc1w, fc1b, fc2w, fc2b, out);     // 5
}

// round 17
// speedup vs baseline: 1.0381x; 1.0381x over previous
#include <cuda_runtime.h>
#include <math.h>

#define NN 100000
#define NE 3200000
#define INF_ 128
#define F1 32
#define F2 16

typedef unsigned long long ull;

// ---------------- scratch (static device globals; zero-init at module load) ----------------
__device__ ull   g_deg64[NN];         // packed: (count << 40) | round(ew * 2^30) sum
__device__ float g_dinv[NN];          // rsqrt(wsum + 1), written by scanA
__device__ int   g_cnt[NN];           // decoded counts, written by scanA
__device__ int   g_row[NN];           // CSR row start (arrival-order block offsets)
__device__ int   g_cur[NN];           // scatter cursors
__device__ int2  g_cedge[NE];         // (src, ew-bits) per CSR slot
__device__ float g_h1[NN * F1];       // x @ W1, then PRESCALED by dinv in scanA
__device__ float g_h2[NN * F2];       // dinv * (hrelu @ W2)  (prescaled)
__device__ float g_q[NN];             // dot(hrelu, fc2_w[0:32]) per node
__device__ int   g_total;             // running block-offset counter (reset in tail)

#define NB 391                        // node blocks of 256 (also gemm1 tile blocks)
#define E4_BLOCKS 3125                // edge blocks (256 thr, 4 edges/thr)

// ---------------- f32x2 packed-FMA helpers (sm_103a FFMA2) ----------------
__device__ __forceinline__ ull pack2(float a, float b) {
    ull r; asm("mov.b64 %0, {%1, %2};" : "=l"(r) : "f"(a), "f"(b)); return r;
}
__device__ __forceinline__ ull fma2(ull a, ull b, ull c) {
    ull d; asm("fma.rn.f32x2 %0, %1, %2, %3;" : "=l"(d) : "l"(a), "l"(b), "l"(c)); return d;
}
__device__ __forceinline__ float2 unpack2(ull v) {
    float x, y; asm("mov.b64 {%0, %1}, %2;" : "=f"(x), "=f"(y) : "l"(v));
    return make_float2(x, y);
}

// ---------------- fat kernel: tiled gemm1 (bid < NB) + packed 64-bit count ----------------
__global__ void __launch_bounds__(256) k_gemm1_count(
        const float* __restrict__ x, const float* __restrict__ W1,
        const int* __restrict__ ei, const float* __restrict__ ew) {
    __shared__ __align__(16) float sW[INF_ * F1];   // [k][f]
    __shared__ __align__(16) float sX[32 * 256];    // [k_local][node_local]
    int bid = blockIdx.x;
    int tid = threadIdx.x;
    if (bid < NB) {
        for (int i = tid; i < INF_ * F1; i += 256) sW[i] = W1[i];
        int nbase = bid * 256;
        int ng = tid >> 2;          // node group 0..63 (4 nodes each)
        int fg = tid & 3;           // feature group 0..3 (8 feats each)
        int f0 = fg * 8;
        ull acc[4][4];
#pragma unroll
        for (int c = 0; c < 4; c++)
#pragma unroll
            for (int p = 0; p < 4; p++) acc[c][p] = 0ull;

        for (int kt = 0; kt < 4; kt++) {
            __syncthreads();
#pragma unroll
            for (int j = 0; j < 8; j++) {
                int flat = tid * 8 + j;     // 0..2047
                int nl = flat >> 3;         // node local 0..255
                int k4 = flat & 7;          // float4 index 0..7
                int n = nbase + nl;
                float4 v = make_float4(0.f, 0.f, 0.f, 0.f);
                if (n < NN)
                    v = *(const float4*)(x + (size_t)n * INF_ + kt * 32 + k4 * 4);
                sX[(k4 * 4 + 0) * 256 + nl] = v.x;
                sX[(k4 * 4 + 1) * 256 + nl] = v.y;
                sX[(k4 * 4 + 2) * 256 + nl] = v.z;
                sX[(k4 * 4 + 3) * 256 + nl] = v.w;
            }
            __syncthreads();
#pragma unroll
            for (int k = 0; k < 32; k++) {
                float4 xv = *(const float4*)&sX[k * 256 + ng * 4];
                const float4* wr = (const float4*)&sW[(kt * 32 + k) * F1 + f0];
                float4 w0 = wr[0], w1 = wr[1];
                ull wp0 = pack2(w0.x, w0.y), wp1 = pack2(w0.z, w0.w);
                ull wp2 = pack2(w1.x, w1.y), wp3 = pack2(w1.z, w1.w);
                float xs[4] = {xv.x, xv.y, xv.z, xv.w};
#pragma unroll
                for (int c = 0; c < 4; c++) {
                    ull xp = pack2(xs[c], xs[c]);
                    acc[c][0] = fma2(xp, wp0, acc[c][0]);
                    acc[c][1] = fma2(xp, wp1, acc[c][1]);
                    acc[c][2] = fma2(xp, wp2, acc[c][2]);
                    acc[c][3] = fma2(xp, wp3, acc[c][3]);
                }
            }
        }
#pragma unroll
        for (int c = 0; c < 4; c++) {
            int n = nbase + ng * 4 + c;
            if (n < NN) {
                float2 v0 = unpack2(acc[c][0]), v1 = unpack2(acc[c][1]);
                float2 v2 = unpack2(acc[c][2]), v3 = unpack2(acc[c][3]);
                float4* o = (float4*)(g_h1 + (size_t)n * F1 + f0);
                o[0] = make_float4(v0.x, v0.y, v1.x, v1.y);
                o[1] = make_float4(v2.x, v2.y, v3.x, v3.y);
            }
        }
    } else {
        // ---- 4 edges per thread: ONE packed 64-bit REDG per edge ----
        int e = ((bid - NB) * 256 + tid) * 4;
        if (e >= NE) return;
        int4   d4 = *(const int4*)  (ei + NE + e);
        float4 w4 = *(const float4*)(ew + e);
        const float SC = 1073741824.0f;   // 2^30
        atomicAdd(&g_deg64[d4.x], (1ull << 40) + (ull)__float2uint_rn(w4.x * SC));
        atomicAdd(&g_deg64[d4.y], (1ull << 40) + (ull)__float2uint_rn(w4.y * SC));
        atomicAdd(&g_deg64[d4.z], (1ull << 40) + (ull)__float2uint_rn(w4.z * SC));
        atomicAdd(&g_deg64[d4.w], (1ull << 40) + (ull)__float2uint_rn(w4.w * SC));
    }
}

// ---- one-kernel scan: decode packed deg, scan, offsets, dinv, PRESCALE h1 ----
__global__ void k_scanA() {
    __shared__ int sh[256];
    __shared__ int s_off;
    int t = threadIdx.x;
    int i = blockIdx.x * 256 + t;
    int cnt = 0;
    float wsum = 0.f;
    if (i < NN) {
        ull v = g_deg64[i];
        cnt = (int)(v >> 40);
        wsum = (float)(v & ((1ull << 40) - 1)) * (1.0f / 1073741824.0f);
    }
    sh[t] = cnt;
    __syncthreads();
    for (int off = 1; off < 256; off <<= 1) {
        int u = (t >= off) ? sh[t - off] : 0;
        __syncthreads();
        sh[t] += u;
        __syncthreads();
    }
    if (t == 255) s_off = atomicAdd(&g_total, sh[255]);
    __syncthreads();
    if (i < NN) {
        int ex = s_off + sh[t] - cnt;
        g_row[i] = ex;
        g_cur[i] = ex;
        g_cnt[i] = cnt;
        float di = rsqrtf(wsum + 1.0f);
        g_dinv[i] = di;
        // prescale h1 row by dinv: h1s = h1 * di
        float4* h = (float4*)(g_h1 + (size_t)i * F1);
#pragma unroll
        for (int j = 0; j < F1 / 4; j++) {
            float4 v = h[j];
            h[j] = make_float4(v.x * di, v.y * di, v.z * di, v.w * di);
        }
    }
}

// 4 edges per thread: cursor-atomic scatter; cedge stores (src, raw ew) — NO dinv loads
__global__ void k_scatter(const int* __restrict__ ei, const float* __restrict__ ew) {
    int e = (blockIdx.x * blockDim.x + threadIdx.x) * 4;
    if (e >= NE) return;
    int4   s4 = *(const int4*)  (ei + e);
    int4   d4 = *(const int4*)  (ei + NE + e);
    float4 w4 = *(const float4*)(ew + e);
    int p0 = atomicAdd(&g_cur[d4.x], 1);
    int p1 = atomicAdd(&g_cur[d4.y], 1);
    int p2 = atomicAdd(&g_cur[d4.z], 1);
    int p3 = atomicAdd(&g_cur[d4.w], 1);
    g_cedge[p0] = make_int2(s4.x, __float_as_int(w4.x));
    g_cedge[p1] = make_int2(s4.y, __float_as_int(w4.y));
    g_cedge[p2] = make_int2(s4.z, __float_as_int(w4.z));
    g_cedge[p3] = make_int2(s4.w, __float_as_int(w4.w));
}

// FUSED layer1 agg + relu + gemm2 + fc-head dot: warp-per-node.
// Edge loop (R14 shape): QUARTER-warp per edge, float4 per lane, 4 clamped gathers.
// x1 = dinv[d]*(sum_e ew*h1s[src] + h1s[d]) + b1 ; h2 written prescaled by dinv.
__global__ void __launch_bounds__(256) k_agg1_fused(
        const float* __restrict__ b1, const float* __restrict__ W2,
        const float* __restrict__ fc2_w) {
    const unsigned FULL = 0xffffffffu;
    __shared__ float sW2[F1 * F2];    // 2 KB [k][f]
    __shared__ float sH[8][F1];       // per-warp hrelu slab
    int tid = threadIdx.x;
    for (int i = tid; i < F1 * F2; i += 256) sW2[i] = W2[i];
    __syncthreads();
    int lane = tid & 31;
    int wid = tid >> 5;
    int n = blockIdx.x * 8 + wid;
    if (n >= NN) return;
    int qt = lane >> 3;      // quarter 0..3 (edge interleave)
    int f4 = lane & 7;       // features 4*f4 .. 4*f4+3
    int beg = g_row[n];
    int cnt = g_cnt[n];
    int end = beg + cnt;
    int niter = (cnt + 15) >> 4;      // 16 edges per warp-iteration, warp-uniform
    float4 a0 = make_float4(0.f, 0.f, 0.f, 0.f);
    float4 a1 = make_float4(0.f, 0.f, 0.f, 0.f);
    int base = beg + qt;
    for (int it = 0; it < niter; it++, base += 16) {
        int i0 = base, i1 = base + 4, i2 = base + 8, i3 = base + 12;
        bool v0 = i0 < end, v1 = i1 < end, v2 = i2 < end, v3 = i3 < end;
        int2 e0 = g_cedge[v0 ? i0 : 0];
        int2 e1 = g_cedge[v1 ? i1 : 0];
        int2 e2 = g_cedge[v2 ? i2 : 0];
        int2 e3 = g_cedge[v3 ? i3 : 0];
        float w0 = v0 ? __int_as_float(e0.y) : 0.f;
        float w1 = v1 ? __int_as_float(e1.y) : 0.f;
        float w2 = v2 ? __int_as_float(e2.y) : 0.f;
        float w3 = v3 ? __int_as_float(e3.y) : 0.f;
        float4 h0 = *(const float4*)(g_h1 + (unsigned)e0.x * F1 + 4 * f4);
        float4 h1 = *(const float4*)(g_h1 + (unsigned)e1.x * F1 + 4 * f4);
        float4 h2 = *(const float4*)(g_h1 + (unsigned)e2.x * F1 + 4 * f4);
        float4 h3 = *(const float4*)(g_h1 + (unsigned)e3.x * F1 + 4 * f4);
        a0.x += w0 * h0.x; a0.y += w0 * h0.y; a0.z += w0 * h0.z; a0.w += w0 * h0.w;
        a1.x += w1 * h1.x; a1.y += w1 * h1.y; a1.z += w1 * h1.z; a1.w += w1 * h1.w;
        a0.x += w2 * h2.x; a0.y += w2 * h2.y; a0.z += w2 * h2.z; a0.w += w2 * h2.w;
        a1.x += w3 * h3.x; a1.y += w3 * h3.y; a1.z += w3 * h3.z; a1.w += w3 * h3.w;
    }
    float4 a = make_float4(a0.x + a1.x, a0.y + a1.y, a0.z + a1.z, a0.w + a1.w);
    a.x += __shfl_down_sync(FULL, a.x, 16);
    a.y += __shfl_down_sync(FULL, a.y, 16);
    a.z += __shfl_down_sync(FULL, a.z, 16);
    a.w += __shfl_down_sync(FULL, a.w, 16);
    a.x += __shfl_down_sync(FULL, a.x, 8);
    a.y += __shfl_down_sync(FULL, a.y, 8);
    a.z += __shfl_down_sync(FULL, a.z, 8);
    a.w += __shfl_down_sync(FULL, a.w, 8);    // lanes 0..7 hold full feature sums
    float di = g_dinv[n];
    float4 hs = *(const float4*)(g_h1 + (unsigned)n * F1 + 4 * f4);   // prescaled h1s[n]
    float4 h;
    h.x = fmaxf(di * (a.x + hs.x) + b1[4 * f4 + 0], 0.f);
    h.y = fmaxf(di * (a.y + hs.y) + b1[4 * f4 + 1], 0.f);
    h.z = fmaxf(di * (a.z + hs.z) + b1[4 * f4 + 2], 0.f);
    h.w = fmaxf(di * (a.w + hs.w) + b1[4 * f4 + 3], 0.f);
    if (lane < 8) *(float4*)&sH[wid][4 * f4] = h;
    __syncwarp();
    // q = dot(hrelu, fc2_w[0:32]) : valid on lanes 0..7, reduce within 8-lane group
    float p = (lane < 8)
        ? h.x * fc2_w[4 * f4] + h.y * fc2_w[4 * f4 + 1]
          + h.z * fc2_w[4 * f4 + 2] + h.w * fc2_w[4 * f4 + 3]
        : 0.f;
    p += __shfl_xor_sync(FULL, p, 4);
    p += __shfl_xor_sync(FULL, p, 2);
    p += __shfl_xor_sync(FULL, p, 1);
    if (lane == 0) g_q[n] = p;
    // h2s[f] = dinv[n] * sum_k hrelu[k]*W2[k][f] : f = lane&15, k-split by half, fold
    const float* s = sH[wid];
    int f = lane & 15;
    int k0 = (lane >> 4) * 16;
    float acc = 0.f, accB = 0.f;
#pragma unroll
    for (int k = 0; k < 16; k += 2) {
        acc  += s[k0 + k]     * sW2[(k0 + k) * F2 + f];
        accB += s[k0 + k + 1] * sW2[(k0 + k + 1) * F2 + f];
    }
    acc += accB;
    acc += __shfl_down_sync(FULL, acc, 16);
    if (lane < 16) g_h2[(unsigned)n * F2 + f] = acc * di;
}

// layer2 aggregation + FC head + tail zeroing; warp-per-node.
// Edge loop: 4 lanes per edge, float4 per lane, 4 clamped gathers (32 edges/iter).
// x2 = dinv[d]*(sum_e ew*h2s[src] + h2s[d]) + b2.
__global__ void k_agg2_final(const float* __restrict__ b2,
                             const float* __restrict__ fc1_w, const float* __restrict__ fc1_b,
                             const float* __restrict__ fc2_w, const float* __restrict__ fc2_b,
                             float* __restrict__ out) {
    const unsigned FULL = 0xffffffffu;
    int lane = threadIdx.x & 31;
    int n = blockIdx.x * (blockDim.x >> 5) + (threadIdx.x >> 5);
    if (n >= NN) return;
    int oc = lane >> 2;      // octant 0..7 (edge interleave)
    int f4 = lane & 3;       // features 4*f4 .. 4*f4+3 (of 16)
    int beg = g_row[n];
    int cnt = g_cnt[n];
    int end = beg + cnt;
    int niter = (cnt + 31) >> 5;      // 32 edges per warp-iteration
    float4 a0 = make_float4(0.f, 0.f, 0.f, 0.f);
    float4 a1 = make_float4(0.f, 0.f, 0.f, 0.f);
    int base = beg + oc;
    for (int it = 0; it < niter; it++, base += 32) {
        int i0 = base, i1 = base + 8, i2 = base + 16, i3 = base + 24;
        bool v0 = i0 < end, v1 = i1 < end, v2 = i2 < end, v3 = i3 < end;
        int2 e0 = g_cedge[v0 ? i0 : 0];
        int2 e1 = g_cedge[v1 ? i1 : 0];
        int2 e2 = g_cedge[v2 ? i2 : 0];
        int2 e3 = g_cedge[v3 ? i3 : 0];
        float w0 = v0 ? __int_as_float(e0.y) : 0.f;
        float w1 = v1 ? __int_as_float(e1.y) : 0.f;
        float w2 = v2 ? __int_as_float(e2.y) : 0.f;
        float w3 = v3 ? __int_as_float(e3.y) : 0.f;
        float4 h0 = *(const float4*)(g_h2 + (unsigned)e0.x * F2 + 4 * f4);
        float4 h1 = *(const float4*)(g_h2 + (unsigned)e1.x * F2 + 4 * f4);
        float4 h2 = *(const float4*)(g_h2 + (unsigned)e2.x * F2 + 4 * f4);
        float4 h3 = *(const float4*)(g_h2 + (unsigned)e3.x * F2 + 4 * f4);
        a0.x += w0 * h0.x; a0.y += w0 * h0.y; a0.z += w0 * h0.z; a0.w += w0 * h0.w;
        a1.x += w1 * h1.x; a1.y += w1 * h1.y; a1.z += w1 * h1.z; a1.w += w1 * h1.w;
        a0.x += w2 * h2.x; a0.y += w2 * h2.y; a0.z += w2 * h2.z; a0.w += w2 * h2.w;
        a1.x += w3 * h3.x; a1.y += w3 * h3.y; a1.z += w3 * h3.z; a1.w += w3 * h3.w;
    }
    float4 a = make_float4(a0.x + a1.x, a0.y + a1.y, a0.z + a1.z, a0.w + a1.w);
    a.x += __shfl_down_sync(FULL, a.x, 16);
    a.y += __shfl_down_sync(FULL, a.y, 16);
    a.z += __shfl_down_sync(FULL, a.z, 16);
    a.w += __shfl_down_sync(FULL, a.w, 16);
    a.x += __shfl_down_sync(FULL, a.x, 8);
    a.y += __shfl_down_sync(FULL, a.y, 8);
    a.z += __shfl_down_sync(FULL, a.z, 8);
    a.w += __shfl_down_sync(FULL, a.w, 8);
    a.x += __shfl_down_sync(FULL, a.x, 4);
    a.y += __shfl_down_sync(FULL, a.y, 4);
    a.z += __shfl_down_sync(FULL, a.z, 4);
    a.w += __shfl_down_sync(FULL, a.w, 4);    // lanes 0..3 hold full feature sums
    float di = g_dinv[n];
    float4 hs = *(const float4*)(g_h2 + (unsigned)n * F2 + 4 * f4);   // prescaled h2s[n]
    float x0 = di * (a.x + hs.x) + b2[4 * f4 + 0];
    float x1v = di * (a.y + hs.y) + b2[4 * f4 + 1];
    float x2v = di * (a.z + hs.z) + b2[4 * f4 + 2];
    float x3 = di * (a.w + hs.w) + b2[4 * f4 + 3];
    // x1f = dot(x2[0:16], fc1_w): per-lane partial over 4 feats, reduce 4-lane group
    float p = x0 * fc1_w[4 * f4] + x1v * fc1_w[4 * f4 + 1]
            + x2v * fc1_w[4 * f4 + 2] + x3 * fc1_w[4 * f4 + 3];
    p += __shfl_xor_sync(FULL, p, 2);
    p += __shfl_xor_sync(FULL, p, 1);         // lanes 0..3 correct
    float x1f = p + fc1_b[0];
    if (lane == 0) {
        float c = 1.0f / (1.0f + expf(-x1f));
        float r = g_q[n] + c * fc2_w[32] + fc2_b[0];
        out[n] = r;
        out[NN + n] = x1f;
    }
    // tail zeroing for the NEXT replay (values already consumed above)
    if (lane == 4) g_deg64[n] = 0ull;
    if (n == 0 && lane == 12) g_total = 0;
}

// ---------------- launch ----------------
extern "C" void kernel_launch(void* const* d_in, const int* in_sizes, int n_in,
                              void* d_out, int out_size) {
    const float* x     = (const float*)d_in[0];
    const int*   ei    = (const int*)  d_in[1];
    const float* ew    = (const float*)d_in[2];
    const float* W1    = (const float*)d_in[3];
    const float* b1    = (const float*)d_in[4];
    const float* W2    = (const float*)d_in[5];
    const float* b2    = (const float*)d_in[6];
    const float* fc1w  = (const float*)d_in[7];
    const float* fc1b  = (const float*)d_in[8];
    const float* fc2w  = (const float*)d_in[9];
    const float* fc2b  = (const float*)d_in[10];
    float* out = (float*)d_out;

    const int TB = 256;
    const int gW = (NN * 32 + TB - 1) / TB;   // warp-per-node: 8 nodes/block
    (void)in_sizes; (void)n_in; (void)out_size;

    k_gemm1_count<<<NB + E4_BLOCKS, TB>>>(x, W1, ei, ew);          // 1
    k_scanA<<<NB, 256>>>();                                        // 2
    k_scatter<<<E4_BLOCKS, TB>>>(ei, ew);                          // 3
    k_agg1_fused<<<gW, TB>>>(b1, W2, fc2w);                        // 4 -> profiled slot
    k_agg2_final<<<gW, TB>>>(b2, fc1w, fc1b, fc2w, fc2b, out);     // 5
}